// round 6
// baseline (speedup 1.0000x reference)
#include <cuda_runtime.h>
#include <cuda_bf16.h>
#include <math.h>
#include <stdint.h>

// ---------------- problem constants ----------------
#define BN    4096          // nodes (B*N)
#define NE    131072        // edges
#define DIMN  480           // 128 + 3*64 + 5*32
#define W3    192           // 3*MSG
#define RBFD  32
#define CUT   5.0f

// ---------------- packed f32x2 helpers ----------------
__device__ __forceinline__ unsigned long long pack2(float lo, float hi) {
    unsigned long long r;
    asm("mov.b64 %0, {%1, %2};" : "=l"(r) : "f"(lo), "f"(hi));
    return r;
}
__device__ __forceinline__ void unpack2(unsigned long long v, float& lo, float& hi) {
    asm("mov.b64 {%0, %1}, %2;" : "=f"(lo), "=f"(hi) : "l"(v));
}
__device__ __forceinline__ void fma2(unsigned long long& d, unsigned long long a,
                                     unsigned long long b) {
    asm("fma.rn.f32x2 %0, %1, %2, %3;" : "=l"(d) : "l"(a), "l"(b), "l"(d));
}

// ---------------- scratch (device globals; no allocation) ----------------
__device__ float g_x[BN * DIMN];                 // node features
__device__ float g_P[BN * W3];                   // per-node projection x[:, :128] @ Wp
__device__ float g_m[BN * 576];                  // per-node segment sums
__device__ float g_rbf[(size_t)NE * RBFD];       // per-edge rbf
__device__ float g_sh[(size_t)NE * 9];           // per-edge sph harmonics
__device__ float g_fcut[NE];                     // per-edge cutoff
__device__ float g_w[(size_t)NE * W3];           // per-EDGE message weights
__device__ int   g_cnt[BN];                      // zero-init at load; re-zeroed by k_scan
__device__ int   g_off[BN + 1];
__device__ int   g_cur[BN];
__device__ int   g_perm[NE];

// ---------------- fused setup: init (32 nodes/CTA) + geometry + count ----------------
#define G_INIT 128
#define G_GEO  512
#define G_CNT  512
__global__ void __launch_bounds__(256) k_setup(const int* __restrict__ z,
                                               const float* __restrict__ mask,
                                               const float* __restrict__ z_emb,
                                               const float* __restrict__ W_in,
                                               const float* __restrict__ ew,
                                               const float* __restrict__ evec,
                                               const int* __restrict__ dst) {
    int bx = blockIdx.x;
    int t = threadIdx.x;
    if (bx < G_INIT) {
        // ---- init: x0 = z_emb[z] @ W_in ----
        __shared__ float sZ[32 * 128];
        __shared__ int   sZi[32];
        __shared__ float sMk[32];
        int n0 = bx * 32;
        if (t < 32) { sZi[t] = z[n0 + t]; sMk[t] = mask[n0 + t]; }
        __syncthreads();
        for (int q = t; q < 32 * 128; q += 256) {
            int nl = q >> 7, k = q & 127;
            sZ[q] = z_emb[sZi[nl] * 128 + k];
        }
        __syncthreads();
        int j = t & 127, g = t >> 7;   // g in {0,1}: 16 nodes each
        float acc[16];
#pragma unroll
        for (int nn = 0; nn < 16; nn++) acc[nn] = 0.f;
#pragma unroll 4
        for (int k = 0; k < 128; k++) {
            float wv = W_in[k * 128 + j];
            const float* zr = &sZ[(g * 16) * 128 + k];
#pragma unroll
            for (int nn = 0; nn < 16; nn++) acc[nn] += zr[nn * 128] * wv;
        }
#pragma unroll
        for (int nn = 0; nn < 16; nn++) {
            int nl = g * 16 + nn;
            g_x[(size_t)(n0 + nl) * DIMN + j] = acc[nn] * sMk[nl];
        }
        for (int idx = t; idx < 32 * 352; idx += 256) {
            int nl = idx / 352, o = 128 + (idx - nl * 352);
            g_x[(size_t)(n0 + nl) * DIMN + o] = 0.f;
        }
    } else if (bx < G_INIT + G_GEO) {
        // ---- geometry ----
        int e = (bx - G_INIT) * 256 + t;
        float len = ew[e];
        float inv = 1.f / fmaxf(len, 1e-8f);
        float x = evec[e * 3 + 0] * inv;
        float y = evec[e * 3 + 1] * inv;
        float zc = evec[e * 3 + 2] * inv;
        float d = fminf(len, CUT);
        const float width = CUT / 31.f;
#pragma unroll
        for (int k = 0; k < RBFD; k++) {
            float c = CUT * (float)k / 31.f;
            float u = (d - c) / width;
            g_rbf[(size_t)e * RBFD + k] = expf(-0.5f * u * u);
        }
        const float s3 = 1.7320508075688772f;
        const float s5 = 2.2360679774997896f;
        const float s15 = 3.872983346207417f;
        float sh[9];
        sh[0] = 1.f;
        sh[1] = s3 * x; sh[2] = s3 * y; sh[3] = s3 * zc;
        sh[4] = s15 * x * y; sh[5] = s15 * y * zc;
        sh[6] = 0.5f * s5 * (3.f * zc * zc - 1.f);
        sh[7] = s15 * x * zc; sh[8] = 0.5f * s15 * (x * x - y * y);
#pragma unroll
        for (int j2 = 0; j2 < 9; j2++) g_sh[(size_t)e * 9 + j2] = sh[j2];
        float tt = fminf(len / CUT, 1.f);
        g_fcut[e] = 0.5f * (cosf(3.14159265358979323846f * tt) + 1.f);
    } else {
        // ---- count ----
        int e = (bx - G_INIT - G_GEO) * 256 + t;
        atomicAdd(&g_cnt[dst[e]], 1);
    }
}

// ---------------- scan (+ self-zero g_cnt for graph replay) ----------------
__global__ void k_scan() {
    __shared__ int part[1024];
    int t = threadIdx.x;
    int base = t * 4;
    int loc[4];
    int s = 0;
#pragma unroll
    for (int i = 0; i < 4; i++) { loc[i] = s; s += g_cnt[base + i]; }
    part[t] = s;
    __syncthreads();
    for (int off = 1; off < 1024; off <<= 1) {
        int v = (t >= off) ? part[t - off] : 0;
        __syncthreads();
        part[t] += v;
        __syncthreads();
    }
    int pre = (t == 0) ? 0 : part[t - 1];
#pragma unroll
    for (int i = 0; i < 4; i++) {
        g_off[base + i] = pre + loc[i];
        g_cur[base + i] = pre + loc[i];
        g_cnt[base + i] = 0;
    }
    if (t == 1023) g_off[BN] = part[1023];
}

__global__ void k_fill(const int* __restrict__ dst) {
    int e = blockIdx.x * 256 + threadIdx.x;
    if (e < NE) {
        int p = atomicAdd(&g_cur[dst[e]], 1);
        g_perm[p] = e;
    }
}

// ---------------- per-node deterministic sort (odd-even in smem, 1 warp/node) ----------------
#define SORT_CAP 1024
__global__ void __launch_bounds__(256) k_sortseg() {
    __shared__ int sbuf[8 * SORT_CAP];
    int warp = threadIdx.x >> 5, lane = threadIdx.x & 31;
    int n = blockIdx.x * 8 + warp;
    int lo = g_off[n], hi = g_off[n + 1];
    int len = hi - lo;
    int* buf = sbuf + warp * SORT_CAP;
    if (len <= 1) return;
    if (len <= SORT_CAP) {
        for (int i = lane; i < len; i += 32) buf[i] = g_perm[lo + i];
        __syncwarp();
        for (int r = 0; r < len; r++) {
            int st = r & 1;
            for (int i = st + 2 * lane; i + 1 < len; i += 64) {
                int a = buf[i], b = buf[i + 1];
                if (a > b) { buf[i] = b; buf[i + 1] = a; }
            }
            __syncwarp();
        }
        for (int i = lane; i < len; i += 32) g_perm[lo + i] = buf[i];
    } else if (lane == 0) {   // fallback (never expected at avg degree 32)
        for (int i = lo + 1; i < hi; i++) {
            int key = g_perm[i];
            int j = i - 1;
            while (j >= lo && g_perm[j] > key) { g_perm[j + 1] = g_perm[j]; j--; }
            g_perm[j + 1] = key;
        }
    }
}

// ---------------- per-node proj GEMM: g_P = x[:, :128] @ Wp[b]  (4096x192x128) ----------------
#define PROJN_SMEM_BYTES (33280 * 4)
__global__ void __launch_bounds__(256) k_projnode(const float* __restrict__ Wpb) {
    extern __shared__ float sm[];
    float* sAT = sm;          // [128][68]
    float* sWp = sm + 8704;   // [128*192]
    int t = threadIdx.x;
    int n0 = blockIdx.x * 64;

    {
        int i = t >> 2, q = t & 3;
        const float* xr = g_x + (size_t)(n0 + i) * DIMN + q * 32;
#pragma unroll
        for (int r = 0; r < 8; r++) {
            float4 v = *(const float4*)(xr + r * 4);
            int k = q * 32 + r * 4;
            sAT[(k + 0) * 68 + i] = v.x;
            sAT[(k + 1) * 68 + i] = v.y;
            sAT[(k + 2) * 68 + i] = v.z;
            sAT[(k + 3) * 68 + i] = v.w;
        }
    }
    for (int q = t; q < 6144; q += 256) ((float4*)sWp)[q] = ((const float4*)Wpb)[q];
    __syncthreads();

    int tx = t & 15, ty = t >> 4;
    int i0 = ty * 4, j0 = tx * 12;
    unsigned long long acc2[4][6];
#pragma unroll
    for (int a = 0; a < 4; a++)
#pragma unroll
        for (int b = 0; b < 6; b++) acc2[a][b] = 0ull;

#pragma unroll 4
    for (int k = 0; k < 128; k++) {
        float4 a0 = *(const float4*)&sAT[k * 68 + i0];
        const float* br = &sWp[k * 192 + j0];
        ulonglong2 q0 = ((const ulonglong2*)br)[0];
        ulonglong2 q1 = ((const ulonglong2*)br)[1];
        ulonglong2 q2 = ((const ulonglong2*)br)[2];
        unsigned long long bb2[6] = {q0.x, q0.y, q1.x, q1.y, q2.x, q2.y};
        float av[4] = {a0.x, a0.y, a0.z, a0.w};
#pragma unroll
        for (int a = 0; a < 4; a++) {
            unsigned long long aa = pack2(av[a], av[a]);
#pragma unroll
            for (int b = 0; b < 6; b++) fma2(acc2[a][b], aa, bb2[b]);
        }
    }
#pragma unroll
    for (int a = 0; a < 4; a++) {
        float accs[12];
#pragma unroll
        for (int b = 0; b < 6; b++) unpack2(acc2[a][b], accs[2 * b], accs[2 * b + 1]);
        float* pr = g_P + (size_t)(n0 + i0 + a) * W3 + j0;
#pragma unroll
        for (int g = 0; g < 3; g++) {
            float4 v;
            v.x = accs[g * 4 + 0]; v.y = accs[g * 4 + 1];
            v.z = accs[g * 4 + 2]; v.w = accs[g * 4 + 3];
            *(float4*)(pr + g * 4) = v;
        }
    }
}

// ---------------- per-edge (edge order): g_w[e] = P[src] * (silu(rbf@rW1+rb1)@rW2 + rb2) * fcut
// smem floats: sRbfT 4224@0, s_rW1 2048@4224, sHT 8448@6272, s_rW2 12288@14720,
//              sFcut 128@27008, s_rb1 64@27136, s_rb2 192@27200, s_src 128@27392
#define EDGE_SMEM_BYTES (27520 * 4)
__global__ void __launch_bounds__(256) k_edge(const float* __restrict__ rW1b,
                                              const float* __restrict__ rb1b,
                                              const float* __restrict__ rW2b,
                                              const float* __restrict__ rb2b,
                                              const int* __restrict__ esrc) {
    extern __shared__ float sm[];
    float* sRbfT = sm;
    float* s_rW1 = sm + 4224;
    float* sHT   = sm + 6272;
    float* s_rW2 = sm + 14720;
    float* sFcut = sm + 27008;
    float* s_rb1 = sm + 27136;
    float* s_rb2 = sm + 27200;
    int*   s_src = (int*)(sm + 27392);

    int t = threadIdx.x;
    int e0 = blockIdx.x * 128;

    {   // rbf tile transposed: 2 threads per edge row, 16 floats each
        int i = t >> 1, half = t & 1;
        const float4* r4 = (const float4*)(g_rbf + (size_t)(e0 + i) * RBFD + half * 16);
#pragma unroll
        for (int q = 0; q < 4; q++) {
            float4 v = r4[q];
            int k = half * 16 + q * 4;
            sRbfT[(k + 0) * 132 + i] = v.x;
            sRbfT[(k + 1) * 132 + i] = v.y;
            sRbfT[(k + 2) * 132 + i] = v.z;
            sRbfT[(k + 3) * 132 + i] = v.w;
        }
    }
    for (int q = t; q < 512; q += 256)  ((float4*)s_rW1)[q] = ((const float4*)rW1b)[q];
    for (int q = t; q < 3072; q += 256) ((float4*)s_rW2)[q] = ((const float4*)rW2b)[q];
    if (t < 128) { sFcut[t] = g_fcut[e0 + t]; s_src[t] = esrc[e0 + t]; }
    if (t < 64)  s_rb1[t] = rb1b[t];
    if (t >= 64 && t < 256) s_rb2[t - 64] = rb2b[t - 64];
    __syncthreads();

    int tx = t & 15, ty = t >> 4;
    int i0 = ty * 8;

    {   // h tile [128][64], thread 8x4 via f32x2
        int c0 = tx * 4;
        unsigned long long hh2[8][2];
#pragma unroll
        for (int a = 0; a < 8; a++) { hh2[a][0] = 0ull; hh2[a][1] = 0ull; }
#pragma unroll 4
        for (int k = 0; k < 32; k++) {
            const float* ar = &sRbfT[k * 132 + i0];
            float4 a0 = *(const float4*)ar;
            float4 a1 = *(const float4*)(ar + 4);
            ulonglong2 bq = *(const ulonglong2*)&s_rW1[k * 64 + c0];
            float av[8] = {a0.x, a0.y, a0.z, a0.w, a1.x, a1.y, a1.z, a1.w};
#pragma unroll
            for (int a = 0; a < 8; a++) {
                unsigned long long aa = pack2(av[a], av[a]);
                fma2(hh2[a][0], aa, bq.x);
                fma2(hh2[a][1], aa, bq.y);
            }
        }
#pragma unroll
        for (int a = 0; a < 8; a++) {
            float hv[4];
            unpack2(hh2[a][0], hv[0], hv[1]);
            unpack2(hh2[a][1], hv[2], hv[3]);
#pragma unroll
            for (int b = 0; b < 4; b++) {
                float v = hv[b] + s_rb1[c0 + b];
                v = v / (1.f + expf(-v));      // silu
                sHT[(c0 + b) * 132 + (i0 + a)] = v;
            }
        }
    }
    __syncthreads();

    {   // r tile [128][192], thread 8x12 via f32x2; w = P[src] * (r+rb2) * fcut -> g_w[e]
        int j0 = tx * 12;
        unsigned long long acc2[8][6];
#pragma unroll
        for (int a = 0; a < 8; a++)
#pragma unroll
            for (int b = 0; b < 6; b++) acc2[a][b] = 0ull;
#pragma unroll 2
        for (int k = 0; k < 64; k++) {
            const float* ar = &sHT[k * 132 + i0];
            float4 a0 = *(const float4*)ar;
            float4 a1 = *(const float4*)(ar + 4);
            const float* br = &s_rW2[k * 192 + j0];
            ulonglong2 q0 = ((const ulonglong2*)br)[0];
            ulonglong2 q1 = ((const ulonglong2*)br)[1];
            ulonglong2 q2 = ((const ulonglong2*)br)[2];
            unsigned long long bb2[6] = {q0.x, q0.y, q1.x, q1.y, q2.x, q2.y};
            float av[8] = {a0.x, a0.y, a0.z, a0.w, a1.x, a1.y, a1.z, a1.w};
#pragma unroll
            for (int a = 0; a < 8; a++) {
                unsigned long long aa = pack2(av[a], av[a]);
#pragma unroll
                for (int b = 0; b < 6; b++) fma2(acc2[a][b], aa, bb2[b]);
            }
        }
        float rb[12];
#pragma unroll
        for (int b = 0; b < 12; b++) rb[b] = s_rb2[j0 + b];
#pragma unroll
        for (int a = 0; a < 8; a++) {
            float accs[12];
#pragma unroll
            for (int b = 0; b < 6; b++) unpack2(acc2[a][b], accs[2 * b], accs[2 * b + 1]);
            float f = sFcut[i0 + a];
            const float* pr = g_P + (size_t)s_src[i0 + a] * W3 + j0;
            float* wout = g_w + (size_t)(e0 + i0 + a) * W3 + j0;
#pragma unroll
            for (int g = 0; g < 3; g++) {
                float4 p = *(const float4*)(pr + g * 4);
                float4 v;
                v.x = (accs[g * 4 + 0] + rb[g * 4 + 0]) * f * p.x;
                v.y = (accs[g * 4 + 1] + rb[g * 4 + 1]) * f * p.y;
                v.z = (accs[g * 4 + 2] + rb[g * 4 + 2]) * f * p.z;
                v.w = (accs[g * 4 + 3] + rb[g * 4 + 3]) * f * p.w;
                *(float4*)(wout + g * 4) = v;
            }
        }
    }
}

// ---------------- segment sum (perm-gathered g_w rows) -> g_m ----------------
__global__ void __launch_bounds__(192) k_seg() {
    int n = blockIdx.x;
    int t = threadIdx.x;
    int lo = g_off[n], hi = g_off[n + 1];
    float acc[5] = {0.f, 0.f, 0.f, 0.f, 0.f};
    for (int p = lo; p < hi; p++) {
        int e = g_perm[p];
        float w = g_w[(size_t)e * W3 + t];
        if (t < 64) {
            acc[0] += w;
        } else if (t < 128) {
            const float* sh = g_sh + (size_t)e * 9 + 1;
#pragma unroll
            for (int d = 0; d < 3; d++) acc[d] += w * sh[d];
        } else {
            const float* sh = g_sh + (size_t)e * 9 + 4;
#pragma unroll
            for (int d = 0; d < 5; d++) acc[d] += w * sh[d];
        }
    }
    float* mr = g_m + (size_t)n * 576;
    if (t < 64) {
        mr[t] = acc[0];
    } else if (t < 128) {
        int c = t - 64;
#pragma unroll
        for (int d = 0; d < 3; d++) mr[64 + c * 3 + d] = acc[d];
    } else {
        int c = t - 128;
#pragma unroll
        for (int d = 0; d < 5; d++) mr[256 + c * 5 + d] = acc[d];
    }
}

// ---------------- apply Wo + residual: x += rs * (m @ Wo), 16 nodes/CTA ----------------
#define OUT_SMEM_BYTES (23552 * 4)
__global__ void __launch_bounds__(256) k_out(const float* __restrict__ Wo0b,
                                             const float* __restrict__ Wo1b,
                                             const float* __restrict__ Wo2b,
                                             const float* __restrict__ res_scale, int b) {
    extern __shared__ float sm[];
    float* sW0 = sm;
    float* sW1 = sm + 8192;
    float* sW2 = sm + 12288;
    float* sM  = sm + 14336;
    int t = threadIdx.x;
    int n0 = blockIdx.x * 16;

    for (int q = t; q < 2048; q += 256) ((float4*)sW0)[q] = ((const float4*)Wo0b)[q];
    for (int q = t; q < 1024; q += 256) ((float4*)sW1)[q] = ((const float4*)Wo1b)[q];
    for (int q = t; q < 512;  q += 256) ((float4*)sW2)[q] = ((const float4*)Wo2b)[q];
    {
        const float4* mg = (const float4*)(g_m + (size_t)n0 * 576);
        for (int q = t; q < 2304; q += 256) ((float4*)sM)[q] = mg[q];
    }
    __syncthreads();

    float rs = res_scale[b];
    for (int idx = t; idx < 16 * 480; idx += 256) {
        int nl = idx / 480, o = idx - nl * 480;
        const float* m = sM + nl * 576;
        float u = 0.f;
        if (o < 128) {
#pragma unroll 8
            for (int k = 0; k < 64; k++) u += m[k] * sW0[k * 128 + o];
        } else if (o < 320) {
            int q = o - 128;
            int c = q / 3, d = q - c * 3;
#pragma unroll 8
            for (int k = 0; k < 64; k++) u += m[64 + k * 3 + d] * sW1[k * 64 + c];
        } else {
            int q = o - 320;
            int c = q / 5, d = q - c * 5;
#pragma unroll 8
            for (int k = 0; k < 64; k++) u += m[256 + k * 5 + d] * sW2[k * 32 + c];
        }
        g_x[(size_t)(n0 + nl) * DIMN + o] += rs * u;
    }
}

// ---------------- irrep RMS norm + mask -> out ----------------
__global__ void __launch_bounds__(256) k_norm(const float* __restrict__ mask,
                                              float* __restrict__ out) {
    __shared__ float r0[256], r1[256], r2[256];
    int n = blockIdx.x, t = threadIdx.x;
    const float* xr = g_x + (size_t)n * DIMN;
    float p0 = 0.f, p1 = 0.f, p2 = 0.f;
    for (int o = t; o < DIMN; o += 256) {
        float v = xr[o];
        float v2 = v * v;
        if (o < 128) p0 += v2;
        else if (o < 320) p1 += v2;
        else p2 += v2;
    }
    r0[t] = p0; r1[t] = p1; r2[t] = p2;
    __syncthreads();
    for (int s = 128; s > 0; s >>= 1) {
        if (t < s) { r0[t] += r0[t + s]; r1[t] += r1[t + s]; r2[t] += r2[t + s]; }
        __syncthreads();
    }
    float inv0 = 1.f / sqrtf(r0[0] / 128.f + 1e-6f);
    float inv1 = 1.f / sqrtf(r1[0] / 64.f + 1e-6f);
    float inv2 = 1.f / sqrtf(r2[0] / 32.f + 1e-6f);
    float m = mask[n];
    for (int o = t; o < DIMN; o += 256) {
        float inv = (o < 128) ? inv0 : ((o < 320) ? inv1 : inv2);
        out[(size_t)n * DIMN + o] = xr[o] * inv * m;
    }
}

// ---------------- launch ----------------
extern "C" void kernel_launch(void* const* d_in, const int* in_sizes, int n_in,
                              void* d_out, int out_size) {
    const int*   z         = (const int*)d_in[0];
    const float* mask      = (const float*)d_in[1];
    const int*   edge_src  = (const int*)d_in[2];
    const int*   edge_dst  = (const int*)d_in[3];
    const float* edge_w    = (const float*)d_in[4];
    const float* edge_vec  = (const float*)d_in[5];
    const float* z_emb     = (const float*)d_in[6];
    const float* W_in      = (const float*)d_in[7];
    const float* Wp        = (const float*)d_in[8];
    const float* rW1       = (const float*)d_in[9];
    const float* rb1       = (const float*)d_in[10];
    const float* rW2       = (const float*)d_in[11];
    const float* rb2       = (const float*)d_in[12];
    const float* Wo0       = (const float*)d_in[13];
    const float* Wo1       = (const float*)d_in[14];
    const float* Wo2       = (const float*)d_in[15];
    const float* res_scale = (const float*)d_in[16];
    float* out = (float*)d_out;

    cudaFuncSetAttribute(k_projnode, cudaFuncAttributeMaxDynamicSharedMemorySize, PROJN_SMEM_BYTES);
    cudaFuncSetAttribute(k_edge, cudaFuncAttributeMaxDynamicSharedMemorySize, EDGE_SMEM_BYTES);
    cudaFuncSetAttribute(k_out, cudaFuncAttributeMaxDynamicSharedMemorySize, OUT_SMEM_BYTES);

    // launch order chosen so that the ncu capture window (observed at launch
    // index 3) lands on k_edge, the presumed-dominant kernel.
    k_setup<<<G_INIT + G_GEO + G_CNT, 256>>>(z, mask, z_emb, W_in, edge_w, edge_vec, edge_dst); // 0
    k_scan<<<1, 1024>>>();                                                                       // 1
    k_projnode<<<BN / 64, 256, PROJN_SMEM_BYTES>>>(Wp);                                          // 2
    k_edge<<<NE / 128, 256, EDGE_SMEM_BYTES>>>(rW1, rb1, rW2, rb2, edge_src);                    // 3 <- ncu
    k_fill<<<NE / 256, 256>>>(edge_dst);                                                         // 4
    k_sortseg<<<BN / 8, 256>>>();                                                                // 5
    k_seg<<<BN, 192>>>();                                                                        // 6
    k_out<<<BN / 16, 256, OUT_SMEM_BYTES>>>(Wo0, Wo1, Wo2, res_scale, 0);                        // 7

    for (int b = 1; b < 3; b++) {
        k_projnode<<<BN / 64, 256, PROJN_SMEM_BYTES>>>(Wp + b * 128 * 192);
        k_edge<<<NE / 128, 256, EDGE_SMEM_BYTES>>>(rW1 + b * 32 * 64, rb1 + b * 64,
                                                   rW2 + b * 64 * 192, rb2 + b * 192, edge_src);
        k_seg<<<BN, 192>>>();
        k_out<<<BN / 16, 256, OUT_SMEM_BYTES>>>(Wo0 + b * 64 * 128, Wo1 + b * 64 * 64,
                                                Wo2 + b * 64 * 32, res_scale, b);
    }
    k_norm<<<BN, 256>>>(mask, out);
}

// round 7
// speedup vs baseline: 1.1349x; 1.1349x over previous
#include <cuda_runtime.h>
#include <cuda_bf16.h>
#include <math.h>
#include <stdint.h>

// ---------------- problem constants ----------------
#define BN    4096          // nodes (B*N)
#define NE    131072        // edges
#define DIMN  480           // 128 + 3*64 + 5*32
#define W3    192           // 3*MSG
#define RBFD  32
#define CUT   5.0f

// ---------------- packed f32x2 helpers ----------------
__device__ __forceinline__ unsigned long long pack2(float lo, float hi) {
    unsigned long long r;
    asm("mov.b64 %0, {%1, %2};" : "=l"(r) : "f"(lo), "f"(hi));
    return r;
}
__device__ __forceinline__ void unpack2(unsigned long long v, float& lo, float& hi) {
    asm("mov.b64 {%0, %1}, %2;" : "=f"(lo), "=f"(hi) : "l"(v));
}
__device__ __forceinline__ void fma2(unsigned long long& d, unsigned long long a,
                                     unsigned long long b) {
    asm("fma.rn.f32x2 %0, %1, %2, %3;" : "=l"(d) : "l"(a), "l"(b), "l"(d));
}

// ---------------- scratch (device globals; no allocation) ----------------
__device__ float g_x[BN * DIMN];                 // node features
__device__ float g_P[BN * W3];                   // per-node projection x[:, :128] @ Wp
__device__ float g_m[BN * 576];                  // per-node segment sums
__device__ float g_rbf[(size_t)NE * RBFD];       // per-edge rbf
__device__ float g_sh[(size_t)NE * 9];           // per-edge sph harmonics
__device__ float g_fcut[NE];                     // per-edge cutoff
__device__ float g_w[(size_t)NE * W3];           // per-EDGE message weights
__device__ int   g_cnt[BN];                      // zero-init at load; re-zeroed by k_scan
__device__ int   g_off[BN + 1];
__device__ int   g_cur[BN];
__device__ int   g_perm[NE];

// ---------------- fused setup: init (32 nodes/CTA) + geometry + count ----------------
#define G_INIT 128
#define G_GEO  512
#define G_CNT  512
__global__ void __launch_bounds__(256) k_setup(const int* __restrict__ z,
                                               const float* __restrict__ mask,
                                               const float* __restrict__ z_emb,
                                               const float* __restrict__ W_in,
                                               const float* __restrict__ ew,
                                               const float* __restrict__ evec,
                                               const int* __restrict__ dst) {
    int bx = blockIdx.x;
    int t = threadIdx.x;
    if (bx < G_INIT) {
        // ---- init: x0 = z_emb[z] @ W_in ----
        __shared__ float sZ[32 * 128];
        __shared__ int   sZi[32];
        __shared__ float sMk[32];
        int n0 = bx * 32;
        if (t < 32) { sZi[t] = z[n0 + t]; sMk[t] = mask[n0 + t]; }
        __syncthreads();
        for (int q = t; q < 32 * 128; q += 256) {
            int nl = q >> 7, k = q & 127;
            sZ[q] = z_emb[sZi[nl] * 128 + k];
        }
        __syncthreads();
        int j = t & 127, g = t >> 7;   // g in {0,1}: 16 nodes each
        float acc[16];
#pragma unroll
        for (int nn = 0; nn < 16; nn++) acc[nn] = 0.f;
#pragma unroll 4
        for (int k = 0; k < 128; k++) {
            float wv = W_in[k * 128 + j];
            const float* zr = &sZ[(g * 16) * 128 + k];
#pragma unroll
            for (int nn = 0; nn < 16; nn++) acc[nn] += zr[nn * 128] * wv;
        }
#pragma unroll
        for (int nn = 0; nn < 16; nn++) {
            int nl = g * 16 + nn;
            g_x[(size_t)(n0 + nl) * DIMN + j] = acc[nn] * sMk[nl];
        }
        for (int idx = t; idx < 32 * 352; idx += 256) {
            int nl = idx / 352, o = 128 + (idx - nl * 352);
            g_x[(size_t)(n0 + nl) * DIMN + o] = 0.f;
        }
    } else if (bx < G_INIT + G_GEO) {
        // ---- geometry ----
        int e = (bx - G_INIT) * 256 + t;
        float len = ew[e];
        float inv = 1.f / fmaxf(len, 1e-8f);
        float x = evec[e * 3 + 0] * inv;
        float y = evec[e * 3 + 1] * inv;
        float zc = evec[e * 3 + 2] * inv;
        float d = fminf(len, CUT);
        const float width = CUT / 31.f;
#pragma unroll
        for (int k = 0; k < RBFD; k++) {
            float c = CUT * (float)k / 31.f;
            float u = (d - c) / width;
            g_rbf[(size_t)e * RBFD + k] = expf(-0.5f * u * u);
        }
        const float s3 = 1.7320508075688772f;
        const float s5 = 2.2360679774997896f;
        const float s15 = 3.872983346207417f;
        float sh[9];
        sh[0] = 1.f;
        sh[1] = s3 * x; sh[2] = s3 * y; sh[3] = s3 * zc;
        sh[4] = s15 * x * y; sh[5] = s15 * y * zc;
        sh[6] = 0.5f * s5 * (3.f * zc * zc - 1.f);
        sh[7] = s15 * x * zc; sh[8] = 0.5f * s15 * (x * x - y * y);
#pragma unroll
        for (int j2 = 0; j2 < 9; j2++) g_sh[(size_t)e * 9 + j2] = sh[j2];
        float tt = fminf(len / CUT, 1.f);
        g_fcut[e] = 0.5f * (cosf(3.14159265358979323846f * tt) + 1.f);
    } else {
        // ---- count ----
        int e = (bx - G_INIT - G_GEO) * 256 + t;
        atomicAdd(&g_cnt[dst[e]], 1);
    }
}

// ---------------- scan (+ self-zero g_cnt for graph replay) ----------------
__global__ void k_scan() {
    __shared__ int part[1024];
    int t = threadIdx.x;
    int base = t * 4;
    int loc[4];
    int s = 0;
#pragma unroll
    for (int i = 0; i < 4; i++) { loc[i] = s; s += g_cnt[base + i]; }
    part[t] = s;
    __syncthreads();
    for (int off = 1; off < 1024; off <<= 1) {
        int v = (t >= off) ? part[t - off] : 0;
        __syncthreads();
        part[t] += v;
        __syncthreads();
    }
    int pre = (t == 0) ? 0 : part[t - 1];
#pragma unroll
    for (int i = 0; i < 4; i++) {
        g_off[base + i] = pre + loc[i];
        g_cur[base + i] = pre + loc[i];
        g_cnt[base + i] = 0;
    }
    if (t == 1023) g_off[BN] = part[1023];
}

__global__ void k_fill(const int* __restrict__ dst) {
    int e = blockIdx.x * 256 + threadIdx.x;
    if (e < NE) {
        int p = atomicAdd(&g_cur[dst[e]], 1);
        g_perm[p] = e;
    }
}

// ---------------- per-node deterministic sort (odd-even in smem, 1 warp/node) ----------------
#define SORT_CAP 1024
__global__ void __launch_bounds__(256) k_sortseg() {
    __shared__ int sbuf[8 * SORT_CAP];
    int warp = threadIdx.x >> 5, lane = threadIdx.x & 31;
    int n = blockIdx.x * 8 + warp;
    int lo = g_off[n], hi = g_off[n + 1];
    int len = hi - lo;
    int* buf = sbuf + warp * SORT_CAP;
    if (len <= 1) return;
    if (len <= SORT_CAP) {
        for (int i = lane; i < len; i += 32) buf[i] = g_perm[lo + i];
        __syncwarp();
        for (int r = 0; r < len; r++) {
            int st = r & 1;
            for (int i = st + 2 * lane; i + 1 < len; i += 64) {
                int a = buf[i], b = buf[i + 1];
                if (a > b) { buf[i] = b; buf[i + 1] = a; }
            }
            __syncwarp();
        }
        for (int i = lane; i < len; i += 32) g_perm[lo + i] = buf[i];
    } else if (lane == 0) {   // fallback (never expected at avg degree 32)
        for (int i = lo + 1; i < hi; i++) {
            int key = g_perm[i];
            int j = i - 1;
            while (j >= lo && g_perm[j] > key) { g_perm[j + 1] = g_perm[j]; j--; }
            g_perm[j + 1] = key;
        }
    }
}

// ---------------- per-node proj GEMM: g_P = x[:, :128] @ Wp[b]  (4096x192x128) ----------------
#define PROJN_SMEM_BYTES (33280 * 4)
__global__ void __launch_bounds__(256) k_projnode(const float* __restrict__ Wpb) {
    extern __shared__ float sm[];
    float* sAT = sm;          // [128][68]
    float* sWp = sm + 8704;   // [128*192]
    int t = threadIdx.x;
    int n0 = blockIdx.x * 64;

    {
        int i = t >> 2, q = t & 3;
        const float* xr = g_x + (size_t)(n0 + i) * DIMN + q * 32;
#pragma unroll
        for (int r = 0; r < 8; r++) {
            float4 v = *(const float4*)(xr + r * 4);
            int k = q * 32 + r * 4;
            sAT[(k + 0) * 68 + i] = v.x;
            sAT[(k + 1) * 68 + i] = v.y;
            sAT[(k + 2) * 68 + i] = v.z;
            sAT[(k + 3) * 68 + i] = v.w;
        }
    }
    for (int q = t; q < 6144; q += 256) ((float4*)sWp)[q] = ((const float4*)Wpb)[q];
    __syncthreads();

    int tx = t & 15, ty = t >> 4;
    int i0 = ty * 4, j0 = tx * 12;
    unsigned long long acc2[4][6];
#pragma unroll
    for (int a = 0; a < 4; a++)
#pragma unroll
        for (int b = 0; b < 6; b++) acc2[a][b] = 0ull;

#pragma unroll 4
    for (int k = 0; k < 128; k++) {
        float4 a0 = *(const float4*)&sAT[k * 68 + i0];
        const float* br = &sWp[k * 192 + j0];
        ulonglong2 q0 = ((const ulonglong2*)br)[0];
        ulonglong2 q1 = ((const ulonglong2*)br)[1];
        ulonglong2 q2 = ((const ulonglong2*)br)[2];
        unsigned long long bb2[6] = {q0.x, q0.y, q1.x, q1.y, q2.x, q2.y};
        float av[4] = {a0.x, a0.y, a0.z, a0.w};
#pragma unroll
        for (int a = 0; a < 4; a++) {
            unsigned long long aa = pack2(av[a], av[a]);
#pragma unroll
            for (int b = 0; b < 6; b++) fma2(acc2[a][b], aa, bb2[b]);
        }
    }
#pragma unroll
    for (int a = 0; a < 4; a++) {
        float accs[12];
#pragma unroll
        for (int b = 0; b < 6; b++) unpack2(acc2[a][b], accs[2 * b], accs[2 * b + 1]);
        float* pr = g_P + (size_t)(n0 + i0 + a) * W3 + j0;
#pragma unroll
        for (int g = 0; g < 3; g++) {
            float4 v;
            v.x = accs[g * 4 + 0]; v.y = accs[g * 4 + 1];
            v.z = accs[g * 4 + 2]; v.w = accs[g * 4 + 3];
            *(float4*)(pr + g * 4) = v;
        }
    }
}

// ---------------- per-edge: g_w[e] = P[src] * (silu(rbf@rW1+rb1)@rW2 + rb2) * fcut ----------
// 64 edges/CTA, 256 threads, 2 CTAs/SM. smem floats:
//   sRbfT [32][68] @0      2176
//   s_rW1 [32*64]  @2176   2048
//   sHT   [64][68] @4224   4352
//   s_rW2 [64*192] @8576   12288
//   sFcut 64       @20864
//   s_rb1 64       @20928
//   s_rb2 192      @20992
//   s_src 64 (int) @21184   -> total 21248 floats = 84992 B
#define EDGE_TILE 64
#define EDGE_SMEM_BYTES (21248 * 4)
__global__ void __launch_bounds__(256, 2) k_edge(const float* __restrict__ rW1b,
                                                 const float* __restrict__ rb1b,
                                                 const float* __restrict__ rW2b,
                                                 const float* __restrict__ rb2b,
                                                 const int* __restrict__ esrc) {
    extern __shared__ float sm[];
    float* sRbfT = sm;
    float* s_rW1 = sm + 2176;
    float* sHT   = sm + 4224;
    float* s_rW2 = sm + 8576;
    float* sFcut = sm + 20864;
    float* s_rb1 = sm + 20928;
    float* s_rb2 = sm + 20992;
    int*   s_src = (int*)(sm + 21184);

    int t = threadIdx.x;
    int e0 = blockIdx.x * EDGE_TILE;

    {   // rbf tile transposed: 4 threads per edge row, 8 floats each
        int i = t >> 2, q = t & 3;
        const float4* r4 = (const float4*)(g_rbf + (size_t)(e0 + i) * RBFD + q * 8);
#pragma unroll
        for (int r = 0; r < 2; r++) {
            float4 v = r4[r];
            int k = q * 8 + r * 4;
            sRbfT[(k + 0) * 68 + i] = v.x;
            sRbfT[(k + 1) * 68 + i] = v.y;
            sRbfT[(k + 2) * 68 + i] = v.z;
            sRbfT[(k + 3) * 68 + i] = v.w;
        }
    }
    for (int q = t; q < 512; q += 256)  ((float4*)s_rW1)[q] = ((const float4*)rW1b)[q];
    for (int q = t; q < 3072; q += 256) ((float4*)s_rW2)[q] = ((const float4*)rW2b)[q];
    if (t < 64)  { sFcut[t] = g_fcut[e0 + t]; s_src[t] = esrc[e0 + t]; s_rb1[t] = rb1b[t]; }
    if (t >= 64 && t < 256) s_rb2[t - 64] = rb2b[t - 64];
    __syncthreads();

    int tx = t & 15, ty = t >> 4;
    int i0 = ty * 4;

    {   // h tile [64 edges][64 cols], thread 4x4 via f32x2
        int c0 = tx * 4;
        unsigned long long hh2[4][2];
#pragma unroll
        for (int a = 0; a < 4; a++) { hh2[a][0] = 0ull; hh2[a][1] = 0ull; }
#pragma unroll 4
        for (int k = 0; k < 32; k++) {
            float4 a0 = *(const float4*)&sRbfT[k * 68 + i0];
            ulonglong2 bq = *(const ulonglong2*)&s_rW1[k * 64 + c0];
            float av[4] = {a0.x, a0.y, a0.z, a0.w};
#pragma unroll
            for (int a = 0; a < 4; a++) {
                unsigned long long aa = pack2(av[a], av[a]);
                fma2(hh2[a][0], aa, bq.x);
                fma2(hh2[a][1], aa, bq.y);
            }
        }
#pragma unroll
        for (int a = 0; a < 4; a++) {
            float hv[4];
            unpack2(hh2[a][0], hv[0], hv[1]);
            unpack2(hh2[a][1], hv[2], hv[3]);
#pragma unroll
            for (int b = 0; b < 4; b++) {
                float v = hv[b] + s_rb1[c0 + b];
                v = v / (1.f + expf(-v));      // silu
                sHT[(c0 + b) * 68 + (i0 + a)] = v;
            }
        }
    }
    __syncthreads();

    {   // r tile [64][192], thread 4x12 via f32x2; w = P[src] * (r+rb2) * fcut -> g_w[e]
        int j0 = tx * 12;
        unsigned long long acc2[4][6];
#pragma unroll
        for (int a = 0; a < 4; a++)
#pragma unroll
            for (int b = 0; b < 6; b++) acc2[a][b] = 0ull;
#pragma unroll 4
        for (int k = 0; k < 64; k++) {
            float4 a0 = *(const float4*)&sHT[k * 68 + i0];
            const float* br = &s_rW2[k * 192 + j0];
            ulonglong2 q0 = ((const ulonglong2*)br)[0];
            ulonglong2 q1 = ((const ulonglong2*)br)[1];
            ulonglong2 q2 = ((const ulonglong2*)br)[2];
            unsigned long long bb2[6] = {q0.x, q0.y, q1.x, q1.y, q2.x, q2.y};
            float av[4] = {a0.x, a0.y, a0.z, a0.w};
#pragma unroll
            for (int a = 0; a < 4; a++) {
                unsigned long long aa = pack2(av[a], av[a]);
#pragma unroll
                for (int b = 0; b < 6; b++) fma2(acc2[a][b], aa, bb2[b]);
            }
        }
        float rb[12];
#pragma unroll
        for (int b = 0; b < 12; b++) rb[b] = s_rb2[j0 + b];
#pragma unroll
        for (int a = 0; a < 4; a++) {
            float accs[12];
#pragma unroll
            for (int b = 0; b < 6; b++) unpack2(acc2[a][b], accs[2 * b], accs[2 * b + 1]);
            float f = sFcut[i0 + a];
            const float* pr = g_P + (size_t)s_src[i0 + a] * W3 + j0;
            float* wout = g_w + (size_t)(e0 + i0 + a) * W3 + j0;
#pragma unroll
            for (int g = 0; g < 3; g++) {
                float4 p = *(const float4*)(pr + g * 4);
                float4 v;
                v.x = (accs[g * 4 + 0] + rb[g * 4 + 0]) * f * p.x;
                v.y = (accs[g * 4 + 1] + rb[g * 4 + 1]) * f * p.y;
                v.z = (accs[g * 4 + 2] + rb[g * 4 + 2]) * f * p.z;
                v.w = (accs[g * 4 + 3] + rb[g * 4 + 3]) * f * p.w;
                *(float4*)(wout + g * 4) = v;
            }
        }
    }
}

// ---------------- segment sum (perm-gathered g_w rows) -> g_m ----------------
__global__ void __launch_bounds__(192) k_seg() {
    int n = blockIdx.x;
    int t = threadIdx.x;
    int lo = g_off[n], hi = g_off[n + 1];
    float acc[5] = {0.f, 0.f, 0.f, 0.f, 0.f};
    for (int p = lo; p < hi; p++) {
        int e = g_perm[p];
        float w = g_w[(size_t)e * W3 + t];
        if (t < 64) {
            acc[0] += w;
        } else if (t < 128) {
            const float* sh = g_sh + (size_t)e * 9 + 1;
#pragma unroll
            for (int d = 0; d < 3; d++) acc[d] += w * sh[d];
        } else {
            const float* sh = g_sh + (size_t)e * 9 + 4;
#pragma unroll
            for (int d = 0; d < 5; d++) acc[d] += w * sh[d];
        }
    }
    float* mr = g_m + (size_t)n * 576;
    if (t < 64) {
        mr[t] = acc[0];
    } else if (t < 128) {
        int c = t - 64;
#pragma unroll
        for (int d = 0; d < 3; d++) mr[64 + c * 3 + d] = acc[d];
    } else {
        int c = t - 128;
#pragma unroll
        for (int d = 0; d < 5; d++) mr[256 + c * 5 + d] = acc[d];
    }
}

// ---------------- apply Wo + residual: x += rs * (m @ Wo), 16 nodes/CTA ----------------
#define OUT_SMEM_BYTES (23552 * 4)
__global__ void __launch_bounds__(256) k_out(const float* __restrict__ Wo0b,
                                             const float* __restrict__ Wo1b,
                                             const float* __restrict__ Wo2b,
                                             const float* __restrict__ res_scale, int b) {
    extern __shared__ float sm[];
    float* sW0 = sm;
    float* sW1 = sm + 8192;
    float* sW2 = sm + 12288;
    float* sM  = sm + 14336;
    int t = threadIdx.x;
    int n0 = blockIdx.x * 16;

    for (int q = t; q < 2048; q += 256) ((float4*)sW0)[q] = ((const float4*)Wo0b)[q];
    for (int q = t; q < 1024; q += 256) ((float4*)sW1)[q] = ((const float4*)Wo1b)[q];
    for (int q = t; q < 512;  q += 256) ((float4*)sW2)[q] = ((const float4*)Wo2b)[q];
    {
        const float4* mg = (const float4*)(g_m + (size_t)n0 * 576);
        for (int q = t; q < 2304; q += 256) ((float4*)sM)[q] = mg[q];
    }
    __syncthreads();

    float rs = res_scale[b];
    for (int idx = t; idx < 16 * 480; idx += 256) {
        int nl = idx / 480, o = idx - nl * 480;
        const float* m = sM + nl * 576;
        float u = 0.f;
        if (o < 128) {
#pragma unroll 8
            for (int k = 0; k < 64; k++) u += m[k] * sW0[k * 128 + o];
        } else if (o < 320) {
            int q = o - 128;
            int c = q / 3, d = q - c * 3;
#pragma unroll 8
            for (int k = 0; k < 64; k++) u += m[64 + k * 3 + d] * sW1[k * 64 + c];
        } else {
            int q = o - 320;
            int c = q / 5, d = q - c * 5;
#pragma unroll 8
            for (int k = 0; k < 64; k++) u += m[256 + k * 5 + d] * sW2[k * 32 + c];
        }
        g_x[(size_t)(n0 + nl) * DIMN + o] += rs * u;
    }
}

// ---------------- irrep RMS norm + mask -> out ----------------
__global__ void __launch_bounds__(256) k_norm(const float* __restrict__ mask,
                                              float* __restrict__ out) {
    __shared__ float r0[256], r1[256], r2[256];
    int n = blockIdx.x, t = threadIdx.x;
    const float* xr = g_x + (size_t)n * DIMN;
    float p0 = 0.f, p1 = 0.f, p2 = 0.f;
    for (int o = t; o < DIMN; o += 256) {
        float v = xr[o];
        float v2 = v * v;
        if (o < 128) p0 += v2;
        else if (o < 320) p1 += v2;
        else p2 += v2;
    }
    r0[t] = p0; r1[t] = p1; r2[t] = p2;
    __syncthreads();
    for (int s = 128; s > 0; s >>= 1) {
        if (t < s) { r0[t] += r0[t + s]; r1[t] += r1[t + s]; r2[t] += r2[t + s]; }
        __syncthreads();
    }
    float inv0 = 1.f / sqrtf(r0[0] / 128.f + 1e-6f);
    float inv1 = 1.f / sqrtf(r1[0] / 64.f + 1e-6f);
    float inv2 = 1.f / sqrtf(r2[0] / 32.f + 1e-6f);
    float m = mask[n];
    for (int o = t; o < DIMN; o += 256) {
        float inv = (o < 128) ? inv0 : ((o < 320) ? inv1 : inv2);
        out[(size_t)n * DIMN + o] = xr[o] * inv * m;
    }
}

// ---------------- launch ----------------
extern "C" void kernel_launch(void* const* d_in, const int* in_sizes, int n_in,
                              void* d_out, int out_size) {
    const int*   z         = (const int*)d_in[0];
    const float* mask      = (const float*)d_in[1];
    const int*   edge_src  = (const int*)d_in[2];
    const int*   edge_dst  = (const int*)d_in[3];
    const float* edge_w    = (const float*)d_in[4];
    const float* edge_vec  = (const float*)d_in[5];
    const float* z_emb     = (const float*)d_in[6];
    const float* W_in      = (const float*)d_in[7];
    const float* Wp        = (const float*)d_in[8];
    const float* rW1       = (const float*)d_in[9];
    const float* rb1       = (const float*)d_in[10];
    const float* rW2       = (const float*)d_in[11];
    const float* rb2       = (const float*)d_in[12];
    const float* Wo0       = (const float*)d_in[13];
    const float* Wo1       = (const float*)d_in[14];
    const float* Wo2       = (const float*)d_in[15];
    const float* res_scale = (const float*)d_in[16];
    float* out = (float*)d_out;

    cudaFuncSetAttribute(k_projnode, cudaFuncAttributeMaxDynamicSharedMemorySize, PROJN_SMEM_BYTES);
    cudaFuncSetAttribute(k_edge, cudaFuncAttributeMaxDynamicSharedMemorySize, EDGE_SMEM_BYTES);
    cudaFuncSetAttribute(k_out, cudaFuncAttributeMaxDynamicSharedMemorySize, OUT_SMEM_BYTES);

    // launch order keeps k_edge at index 3 (where the ncu capture window lands).
    k_setup<<<G_INIT + G_GEO + G_CNT, 256>>>(z, mask, z_emb, W_in, edge_w, edge_vec, edge_dst); // 0
    k_scan<<<1, 1024>>>();                                                                       // 1
    k_projnode<<<BN / 64, 256, PROJN_SMEM_BYTES>>>(Wp);                                          // 2
    k_edge<<<NE / EDGE_TILE, 256, EDGE_SMEM_BYTES>>>(rW1, rb1, rW2, rb2, edge_src);              // 3 <- ncu
    k_fill<<<NE / 256, 256>>>(edge_dst);                                                         // 4
    k_sortseg<<<BN / 8, 256>>>();                                                                // 5
    k_seg<<<BN, 192>>>();                                                                        // 6
    k_out<<<BN / 16, 256, OUT_SMEM_BYTES>>>(Wo0, Wo1, Wo2, res_scale, 0);                        // 7

    for (int b = 1; b < 3; b++) {
        k_projnode<<<BN / 64, 256, PROJN_SMEM_BYTES>>>(Wp + b * 128 * 192);
        k_edge<<<NE / EDGE_TILE, 256, EDGE_SMEM_BYTES>>>(rW1 + b * 32 * 64, rb1 + b * 64,
                                                         rW2 + b * 64 * 192, rb2 + b * 192,
                                                         edge_src);
        k_seg<<<BN, 192>>>();
        k_out<<<BN / 16, 256, OUT_SMEM_BYTES>>>(Wo0 + b * 64 * 128, Wo1 + b * 64 * 64,
                                                Wo2 + b * 64 * 32, res_scale, b);
    }
    k_norm<<<BN, 256>>>(mask, out);
}